// round 1
// baseline (speedup 1.0000x reference)
#include <cuda_runtime.h>
#include <cstdint>

// Problem constants
#define CONTEXT 256
#define EMB     384
#define HD      64
#define NBATCH  512
#define BT      (NBATCH * CONTEXT)   // 131072 rows

// Scratch for q, k, v (tf32-rounded fp32 bit patterns). Static __device__
// arrays (no allocation allowed).
__device__ float g_q[BT * HD];
__device__ float g_k[BT * HD];
__device__ float g_v[BT * HD];

// ---------------------------------------------------------------------------
// Helpers
// ---------------------------------------------------------------------------
__device__ __forceinline__ unsigned f2tf(float f) {
    unsigned u;
    asm("cvt.rna.tf32.f32 %0, %1;" : "=r"(u) : "f"(f));
    return u;
}

// D += A * B, m16n8k8 tf32. A row-major frag (4 regs), B col-major frag (2 regs).
__device__ __forceinline__ void mma_tf32(float* d, const unsigned* a, const unsigned* b) {
    asm volatile(
        "mma.sync.aligned.m16n8k8.row.col.f32.tf32.tf32.f32 "
        "{%0,%1,%2,%3}, {%4,%5,%6,%7}, {%8,%9}, {%0,%1,%2,%3};"
        : "+f"(d[0]), "+f"(d[1]), "+f"(d[2]), "+f"(d[3])
        : "r"(a[0]), "r"(a[1]), "r"(a[2]), "r"(a[3]), "r"(b[0]), "r"(b[1]));
}

// ---------------------------------------------------------------------------
// Kernel 1: QKV projection.  out[row, h] = sum_k x[row, k] * W[k, h]
// Grid: (3, 1024).  blockIdx.x selects {q,k,v}; blockIdx.y selects a 128-row
// M-tile. blockIdx.x is fastest-varying so the three blocks sharing an x tile
// are launched adjacently -> x tile served from L2 for 2 of the 3 reads.
// Block: 256 threads = 8 warps, warp grid 4(m) x 2(n).
// Per warp: 32 rows x 32 cols = 2 m16-tiles x 4 n8-tiles.
// ---------------------------------------------------------------------------
__global__ void __launch_bounds__(256) qkv_kernel(
    const float* __restrict__ x,
    const float* __restrict__ Wq,
    const float* __restrict__ Wk,
    const float* __restrict__ Wv)
{
    const int which = blockIdx.x;           // 0=q, 1=k, 2=v
    const int row0  = blockIdx.y * 128;

    const float* W    = (which == 0) ? Wq : (which == 1) ? Wk : Wv;
    float*       outp = (which == 0) ? g_q : (which == 1) ? g_k : g_v;
    const float  scale = (which == 0) ? 0.125f : 1.0f;   // H^-1/2 folded into q

    // A: [128 rows][36 cols] (pad 32->36: conflict-free frag loads, 16B-aligned rows)
    // B: [32 k][72 n]        (pad 64->72: conflict-free frag loads)
    __shared__ float As[128 * 36];
    __shared__ float Ws[32 * 72];

    const int tid  = threadIdx.x;
    const int lane = tid & 31;
    const int warp = tid >> 5;
    const int g    = lane >> 2;   // groupID
    const int c    = lane & 3;    // threadID_in_group
    const int wm   = warp >> 1;   // 0..3
    const int wn   = warp & 1;    // 0..1

    float acc[2][4][4];
    #pragma unroll
    for (int i = 0; i < 2; i++)
        #pragma unroll
        for (int j = 0; j < 4; j++)
            #pragma unroll
            for (int r = 0; r < 4; r++) acc[i][j][r] = 0.f;

    for (int kb = 0; kb < 12; kb++) {
        const int k0 = kb * 32;

        // Load x tile: 128 x 32, convert to tf32 while staging.
        #pragma unroll
        for (int i = 0; i < 4; i++) {
            int li = tid + i * 256;          // 0..1023
            int r  = li >> 3;
            int c4 = (li & 7) * 4;
            float4 v = *reinterpret_cast<const float4*>(&x[(row0 + r) * EMB + k0 + c4]);
            float4 t;
            t.x = __uint_as_float(f2tf(v.x));
            t.y = __uint_as_float(f2tf(v.y));
            t.z = __uint_as_float(f2tf(v.z));
            t.w = __uint_as_float(f2tf(v.w));
            *reinterpret_cast<float4*>(&As[r * 36 + c4]) = t;
        }
        // Load W tile: 32 x 64
        #pragma unroll
        for (int i = 0; i < 2; i++) {
            int li = tid + i * 256;          // 0..511
            int r  = li >> 4;
            int c4 = (li & 15) * 4;
            float4 v = *reinterpret_cast<const float4*>(&W[(k0 + r) * HD + c4]);
            float4 t;
            t.x = __uint_as_float(f2tf(v.x));
            t.y = __uint_as_float(f2tf(v.y));
            t.z = __uint_as_float(f2tf(v.z));
            t.w = __uint_as_float(f2tf(v.w));
            *reinterpret_cast<float4*>(&Ws[r * 72 + c4]) = t;
        }
        __syncthreads();

        #pragma unroll
        for (int ks = 0; ks < 4; ks++) {
            const int kk = ks * 8;
            unsigned a[2][4];
            #pragma unroll
            for (int mt = 0; mt < 2; mt++) {
                int base = (wm * 32 + mt * 16 + g) * 36 + kk + c;
                a[mt][0] = __float_as_uint(As[base]);
                a[mt][1] = __float_as_uint(As[base + 8 * 36]);
                a[mt][2] = __float_as_uint(As[base + 4]);
                a[mt][3] = __float_as_uint(As[base + 8 * 36 + 4]);
            }
            unsigned bf[4][2];
            #pragma unroll
            for (int nt = 0; nt < 4; nt++) {
                int bb = (kk + c) * 72 + wn * 32 + nt * 8 + g;
                bf[nt][0] = __float_as_uint(Ws[bb]);
                bf[nt][1] = __float_as_uint(Ws[bb + 4 * 72]);
            }
            #pragma unroll
            for (int mt = 0; mt < 2; mt++)
                #pragma unroll
                for (int nt = 0; nt < 4; nt++)
                    mma_tf32(acc[mt][nt], a[mt], bf[nt]);
        }
        __syncthreads();
    }

    // Epilogue: scale (q only), round to tf32 so kernel 2 consumes bits directly.
    #pragma unroll
    for (int mt = 0; mt < 2; mt++) {
        int r0 = row0 + wm * 32 + mt * 16 + g;
        #pragma unroll
        for (int nt = 0; nt < 4; nt++) {
            int col = wn * 32 + nt * 8 + 2 * c;
            float2 v0, v1;
            v0.x = __uint_as_float(f2tf(acc[mt][nt][0] * scale));
            v0.y = __uint_as_float(f2tf(acc[mt][nt][1] * scale));
            v1.x = __uint_as_float(f2tf(acc[mt][nt][2] * scale));
            v1.y = __uint_as_float(f2tf(acc[mt][nt][3] * scale));
            *reinterpret_cast<float2*>(&outp[r0 * HD + col])       = v0;
            *reinterpret_cast<float2*>(&outp[(r0 + 8) * HD + col]) = v1;
        }
    }
}

// ---------------------------------------------------------------------------
// Kernel 2: causal attention, one block per batch (512 blocks, 256 threads).
// K,V staged in smem as [256][72] fp32/tf32 (stride 72 -> conflict-free for
// both B-fragment patterns). Flash-attention-2 online softmax.
// Each warp handles q-tiles w and 15-w (16 rows each) -> exactly 5 causal
// key-chunk iterations per warp (perfect balance).
// ---------------------------------------------------------------------------
#define KV_STRIDE 72
#define SMEM_BYTES (2 * CONTEXT * KV_STRIDE * 4)

__global__ void __launch_bounds__(256, 1) attn_kernel(float* __restrict__ out)
{
    extern __shared__ float sm[];
    float* kS = sm;                       // [256][72]
    float* vS = sm + CONTEXT * KV_STRIDE; // [256][72]

    const int b   = blockIdx.x;
    const int tid = threadIdx.x;

    const float* kg = g_k + b * (CONTEXT * HD);
    const float* vg = g_v + b * (CONTEXT * HD);

    #pragma unroll
    for (int i = 0; i < 16; i++) {
        int fi = tid + i * 256;          // 0..4095 float4s per array
        int r  = fi >> 4;
        int c4 = (fi & 15) * 4;
        *reinterpret_cast<float4*>(&kS[r * KV_STRIDE + c4]) =
            *reinterpret_cast<const float4*>(&kg[r * HD + c4]);
        *reinterpret_cast<float4*>(&vS[r * KV_STRIDE + c4]) =
            *reinterpret_cast<const float4*>(&vg[r * HD + c4]);
    }
    __syncthreads();

    const int lane = tid & 31;
    const int warp = tid >> 5;
    const int g    = lane >> 2;
    const int c    = lane & 3;
    const float L2E = 1.44269504f;

    for (int pass = 0; pass < 2; pass++) {
        const int t = pass ? (15 - warp) : warp;   // q-tile index, rows [16t, 16t+16)

        // Preload q A-fragments for all 8 k-steps (H=64). Bits are already tf32.
        const float* qg = g_q + (b * CONTEXT + t * 16) * HD;
        unsigned qa[8][4];
        #pragma unroll
        for (int kt = 0; kt < 8; kt++) {
            int col = kt * 8 + c;
            qa[kt][0] = __float_as_uint(qg[g * HD + col]);
            qa[kt][1] = __float_as_uint(qg[(g + 8) * HD + col]);
            qa[kt][2] = __float_as_uint(qg[g * HD + col + 4]);
            qa[kt][3] = __float_as_uint(qg[(g + 8) * HD + col + 4]);
        }

        float o[8][4];
        #pragma unroll
        for (int nt = 0; nt < 8; nt++)
            #pragma unroll
            for (int r = 0; r < 4; r++) o[nt][r] = 0.f;

        float m0 = -1e30f, m1 = -1e30f, l0 = 0.f, l1 = 0.f;
        const int diag = t >> 2;                 // diagonal chunk index
        const int nch  = diag + 1;

        for (int jc = 0; jc < nch; jc++) {
            // ---- scores S[16][64] over key chunk jc ----
            float s[8][4];
            #pragma unroll
            for (int nt = 0; nt < 8; nt++)
                #pragma unroll
                for (int r = 0; r < 4; r++) s[nt][r] = 0.f;

            #pragma unroll
            for (int nt = 0; nt < 8; nt++) {
                const float* kr = &kS[(jc * 64 + nt * 8 + g) * KV_STRIDE];
                #pragma unroll
                for (int kt = 0; kt < 8; kt++) {
                    unsigned bf[2];
                    bf[0] = __float_as_uint(kr[kt * 8 + c]);
                    bf[1] = __float_as_uint(kr[kt * 8 + c + 4]);
                    mma_tf32(s[nt], qa[kt], bf);
                }
            }

            // ---- causal mask (diagonal chunk only) ----
            if (jc == diag) {
                int rowg = t * 16 + g;
                #pragma unroll
                for (int nt = 0; nt < 8; nt++) {
                    int colg = jc * 64 + nt * 8 + 2 * c;
                    if (colg     > rowg)     s[nt][0] = -1e30f;
                    if (colg + 1 > rowg)     s[nt][1] = -1e30f;
                    if (colg     > rowg + 8) s[nt][2] = -1e30f;
                    if (colg + 1 > rowg + 8) s[nt][3] = -1e30f;
                }
            }

            // ---- online softmax update ----
            float mx0 = -1e30f, mx1 = -1e30f;
            #pragma unroll
            for (int nt = 0; nt < 8; nt++) {
                mx0 = fmaxf(mx0, fmaxf(s[nt][0], s[nt][1]));
                mx1 = fmaxf(mx1, fmaxf(s[nt][2], s[nt][3]));
            }
            mx0 = fmaxf(mx0, __shfl_xor_sync(0xffffffffu, mx0, 1));
            mx0 = fmaxf(mx0, __shfl_xor_sync(0xffffffffu, mx0, 2));
            mx1 = fmaxf(mx1, __shfl_xor_sync(0xffffffffu, mx1, 1));
            mx1 = fmaxf(mx1, __shfl_xor_sync(0xffffffffu, mx1, 2));

            float mn0 = fmaxf(m0, mx0), mn1 = fmaxf(m1, mx1);
            float al0 = exp2f((m0 - mn0) * L2E);
            float al1 = exp2f((m1 - mn1) * L2E);
            m0 = mn0; m1 = mn1;

            float rs0 = 0.f, rs1 = 0.f;
            #pragma unroll
            for (int nt = 0; nt < 8; nt++) {
                s[nt][0] = exp2f((s[nt][0] - mn0) * L2E);
                s[nt][1] = exp2f((s[nt][1] - mn0) * L2E);
                s[nt][2] = exp2f((s[nt][2] - mn1) * L2E);
                s[nt][3] = exp2f((s[nt][3] - mn1) * L2E);
                rs0 += s[nt][0] + s[nt][1];
                rs1 += s[nt][2] + s[nt][3];
            }
            l0 = l0 * al0 + rs0;
            l1 = l1 * al1 + rs1;
            #pragma unroll
            for (int nt = 0; nt < 8; nt++) {
                o[nt][0] *= al0; o[nt][1] *= al0;
                o[nt][2] *= al1; o[nt][3] *= al1;
            }

            // ---- O += P @ V ----
            // P is in C-fragment layout; rearrange to A-fragment layout with
            // intra-quad shuffles (tf32 m16n8k8 A/C layouts differ).
            const int srcA = (lane & ~3) | (c >> 1);
            const int srcB = srcA + 2;
            const bool odd = (c & 1);
            #pragma unroll
            for (int kt = 0; kt < 8; kt++) {
                float v0 = __shfl_sync(0xffffffffu, s[kt][0], srcA);
                float v1 = __shfl_sync(0xffffffffu, s[kt][1], srcA);
                float v2 = __shfl_sync(0xffffffffu, s[kt][2], srcA);
                float v3 = __shfl_sync(0xffffffffu, s[kt][3], srcA);
                float w0 = __shfl_sync(0xffffffffu, s[kt][0], srcB);
                float w1 = __shfl_sync(0xffffffffu, s[kt][1], srcB);
                float w2 = __shfl_sync(0xffffffffu, s[kt][2], srcB);
                float w3 = __shfl_sync(0xffffffffu, s[kt][3], srcB);
                unsigned pa[4];
                pa[0] = f2tf(odd ? v1 : v0);
                pa[1] = f2tf(odd ? v3 : v2);
                pa[2] = f2tf(odd ? w1 : w0);
                pa[3] = f2tf(odd ? w3 : w2);

                const int krow0 = (jc * 64 + kt * 8 + c) * KV_STRIDE;
                const int krow1 = (jc * 64 + kt * 8 + c + 4) * KV_STRIDE;
                #pragma unroll
                for (int nt = 0; nt < 8; nt++) {
                    unsigned bv[2];
                    bv[0] = __float_as_uint(vS[krow0 + nt * 8 + g]);
                    bv[1] = __float_as_uint(vS[krow1 + nt * 8 + g]);
                    mma_tf32(o[nt], pa, bv);
                }
            }
        }

        // ---- finalize: divide by row sums, write out ----
        l0 += __shfl_xor_sync(0xffffffffu, l0, 1);
        l0 += __shfl_xor_sync(0xffffffffu, l0, 2);
        l1 += __shfl_xor_sync(0xffffffffu, l1, 1);
        l1 += __shfl_xor_sync(0xffffffffu, l1, 2);
        float inv0 = 1.f / l0, inv1 = 1.f / l1;

        float* og = out + (b * CONTEXT + t * 16) * HD;
        #pragma unroll
        for (int nt = 0; nt < 8; nt++) {
            int col = nt * 8 + 2 * c;
            float2 u0, u1;
            u0.x = o[nt][0] * inv0; u0.y = o[nt][1] * inv0;
            u1.x = o[nt][2] * inv1; u1.y = o[nt][3] * inv1;
            *reinterpret_cast<float2*>(&og[g * HD + col])       = u0;
            *reinterpret_cast<float2*>(&og[(g + 8) * HD + col]) = u1;
        }
    }
}

// ---------------------------------------------------------------------------
// Launch
// ---------------------------------------------------------------------------
extern "C" void kernel_launch(void* const* d_in, const int* in_sizes, int n_in,
                              void* d_out, int out_size)
{
    (void)in_sizes; (void)n_in; (void)out_size;
    const float* x  = (const float*)d_in[0];
    const float* Wq = (const float*)d_in[1];
    const float* Wk = (const float*)d_in[2];
    const float* Wv = (const float*)d_in[3];
    float* out = (float*)d_out;

    qkv_kernel<<<dim3(3, BT / 128), 256>>>(x, Wq, Wk, Wv);

    cudaFuncSetAttribute(attn_kernel,
                         cudaFuncAttributeMaxDynamicSharedMemorySize, SMEM_BYTES);
    attn_kernel<<<NBATCH, 256, SMEM_BYTES>>>(out);
}

// round 2
// speedup vs baseline: 1.0802x; 1.0802x over previous
#include <cuda_runtime.h>
#include <cstdint>

#define CONTEXT 256
#define EMB     384
#define HD      64
#define NBATCH  512
#define BT      (NBATCH * CONTEXT)   // 131072 rows

// Scratch for q, k, v (tf32-rounded fp32 bit patterns).
__device__ float g_q[BT * HD];
__device__ float g_k[BT * HD];
__device__ float g_v[BT * HD];

// ---------------------------------------------------------------------------
__device__ __forceinline__ unsigned f2tf(float f) {
    unsigned u;
    asm("cvt.rna.tf32.f32 %0, %1;" : "=r"(u) : "f"(f));
    return u;
}

__device__ __forceinline__ void mma_tf32(float* d, const unsigned* a, const unsigned* b) {
    asm volatile(
        "mma.sync.aligned.m16n8k8.row.col.f32.tf32.tf32.f32 "
        "{%0,%1,%2,%3}, {%4,%5,%6,%7}, {%8,%9}, {%0,%1,%2,%3};"
        : "+f"(d[0]), "+f"(d[1]), "+f"(d[2]), "+f"(d[3])
        : "r"(a[0]), "r"(a[1]), "r"(a[2]), "r"(a[3]), "r"(b[0]), "r"(b[1]));
}

// ---------------------------------------------------------------------------
// Fused QKV: one pass over x. Each block computes a 128-row tile of
// [q|k|v] = x @ [Wq|Wk|Wv]  (128 x 192 output, K=384).
// 512 threads = 16 warps, warp grid 4(m) x 4(n): warp tile 32 x 48.
// Double-buffered smem, register-prefetched global loads.
// q columns are pre-scaled by H^-1/2 and everything is tf32-rounded on store.
// ---------------------------------------------------------------------------
#define AS_STRIDE 36     // 32 + 4 pad: conflict-free A-frag LDS
#define BS_STRIDE 200    // 192 + 8 pad: conflict-free B-frag LDS
#define AS_ELEMS  (128 * AS_STRIDE)
#define BS_ELEMS  (32 * BS_STRIDE)
#define QKV_SMEM  ((2 * AS_ELEMS + 2 * BS_ELEMS) * 4)

__global__ void __launch_bounds__(512, 1) qkv_fused(
    const float* __restrict__ x,
    const float* __restrict__ Wq,
    const float* __restrict__ Wk,
    const float* __restrict__ Wv)
{
    extern __shared__ float smf[];
    float* As = smf;                     // [2][128][36]
    float* Bs = smf + 2 * AS_ELEMS;      // [2][32][200]

    const int row0 = blockIdx.x * 128;
    const int tid  = threadIdx.x;
    const int lane = tid & 31;
    const int warp = tid >> 5;
    const int g    = lane >> 2;
    const int c    = lane & 3;
    const int wm   = warp >> 2;          // 0..3 -> rows wm*32
    const int wn   = warp & 3;           // 0..3 -> cols wn*48

    float acc[2][6][4];
    #pragma unroll
    for (int mt = 0; mt < 2; mt++)
        #pragma unroll
        for (int nt = 0; nt < 6; nt++)
            #pragma unroll
            for (int r = 0; r < 4; r++) acc[mt][nt][r] = 0.f;

    // prefetch registers
    float4 xr[2];
    float4 br[3];

    // ---- load tile kb from global into registers ----
    auto ldg_tile = [&](int kb) {
        const int k0 = kb * 32;
        #pragma unroll
        for (int i = 0; i < 2; i++) {
            int li = tid + i * 512;              // 0..1023
            int r  = li >> 3;
            int c4 = (li & 7) * 4;
            xr[i] = *reinterpret_cast<const float4*>(&x[(row0 + r) * EMB + k0 + c4]);
        }
        #pragma unroll
        for (int i = 0; i < 3; i++) {
            int li  = tid + i * 512;             // 0..1535
            int r   = li / 48;
            int cc  = (li % 48) * 4;             // 0..188
            int w   = cc >> 6;                   // 0=q,1=k,2=v
            int col = cc & 63;
            const float* Wp = (w == 0) ? Wq : (w == 1) ? Wk : Wv;
            br[i] = *reinterpret_cast<const float4*>(&Wp[(k0 + r) * HD + col]);
        }
    };

    // ---- convert + store prefetched registers into smem buffer `buf` ----
    auto sts_tile = [&](int buf) {
        float* Ab = As + buf * AS_ELEMS;
        float* Bb = Bs + buf * BS_ELEMS;
        #pragma unroll
        for (int i = 0; i < 2; i++) {
            int li = tid + i * 512;
            int r  = li >> 3;
            int c4 = (li & 7) * 4;
            float4 t;
            t.x = __uint_as_float(f2tf(xr[i].x));
            t.y = __uint_as_float(f2tf(xr[i].y));
            t.z = __uint_as_float(f2tf(xr[i].z));
            t.w = __uint_as_float(f2tf(xr[i].w));
            *reinterpret_cast<float4*>(&Ab[r * AS_STRIDE + c4]) = t;
        }
        #pragma unroll
        for (int i = 0; i < 3; i++) {
            int li = tid + i * 512;
            int r  = li / 48;
            int cc = (li % 48) * 4;
            float4 t;
            t.x = __uint_as_float(f2tf(br[i].x));
            t.y = __uint_as_float(f2tf(br[i].y));
            t.z = __uint_as_float(f2tf(br[i].z));
            t.w = __uint_as_float(f2tf(br[i].w));
            *reinterpret_cast<float4*>(&Bb[r * BS_STRIDE + cc]) = t;
        }
    };

    ldg_tile(0);
    sts_tile(0);
    __syncthreads();

    for (int kb = 0; kb < 12; kb++) {
        const int buf = kb & 1;
        if (kb < 11) ldg_tile(kb + 1);

        const float* Ab = As + buf * AS_ELEMS;
        const float* Bb = Bs + buf * BS_ELEMS;

        #pragma unroll
        for (int ks = 0; ks < 4; ks++) {
            const int kk = ks * 8;
            unsigned a[2][4];
            #pragma unroll
            for (int mt = 0; mt < 2; mt++) {
                int base = (wm * 32 + mt * 16 + g) * AS_STRIDE + kk + c;
                a[mt][0] = __float_as_uint(Ab[base]);
                a[mt][1] = __float_as_uint(Ab[base + 8 * AS_STRIDE]);
                a[mt][2] = __float_as_uint(Ab[base + 4]);
                a[mt][3] = __float_as_uint(Ab[base + 8 * AS_STRIDE + 4]);
            }
            unsigned bf[6][2];
            #pragma unroll
            for (int nt = 0; nt < 6; nt++) {
                int bb = (kk + c) * BS_STRIDE + wn * 48 + nt * 8 + g;
                bf[nt][0] = __float_as_uint(Bb[bb]);
                bf[nt][1] = __float_as_uint(Bb[bb + 4 * BS_STRIDE]);
            }
            #pragma unroll
            for (int mt = 0; mt < 2; mt++)
                #pragma unroll
                for (int nt = 0; nt < 6; nt++)
                    mma_tf32(acc[mt][nt], a[mt], bf[nt]);
        }

        if (kb < 11) sts_tile(buf ^ 1);
        __syncthreads();
    }

    // ---- epilogue: pick q/k/v target per 8-col tile, scale q, tf32-round ----
    #pragma unroll
    for (int mt = 0; mt < 2; mt++) {
        const int r0 = row0 + wm * 32 + mt * 16 + g;
        #pragma unroll
        for (int nt = 0; nt < 6; nt++) {
            const int cb    = wn * 48 + nt * 8;     // global output col base
            const int which = cb >> 6;              // 8-col tiles never cross 64
            float* outp = (which == 0) ? g_q : (which == 1) ? g_k : g_v;
            const float scale = (which == 0) ? 0.125f : 1.0f;
            const int col = (cb & 63) + 2 * c;
            float2 v0, v1;
            v0.x = __uint_as_float(f2tf(acc[mt][nt][0] * scale));
            v0.y = __uint_as_float(f2tf(acc[mt][nt][1] * scale));
            v1.x = __uint_as_float(f2tf(acc[mt][nt][2] * scale));
            v1.y = __uint_as_float(f2tf(acc[mt][nt][3] * scale));
            *reinterpret_cast<float2*>(&outp[r0 * HD + col])       = v0;
            *reinterpret_cast<float2*>(&outp[(r0 + 8) * HD + col]) = v1;
        }
    }
}

// ---------------------------------------------------------------------------
// Kernel 2: causal attention, one block per batch (512 blocks, 256 threads).
// kS stride 76 (conflict-free K-frag loads), vS stride 72 (conflict-free
// V-frag loads). Flash-attention-2 online softmax. Warp w handles q-tiles
// w and 15-w -> exactly 5 key chunks per warp (perfect causal balance).
// Scores loop is kt-outer / nt-inner: 8 independent MMA accumulators.
// ---------------------------------------------------------------------------
#define KSTRIDE 76
#define VSTRIDE 72
#define ATTN_SMEM (CONTEXT * (KSTRIDE + VSTRIDE) * 4)

__global__ void __launch_bounds__(256, 1) attn_kernel(float* __restrict__ out)
{
    extern __shared__ float sm[];
    float* kS = sm;                      // [256][76]
    float* vS = sm + CONTEXT * KSTRIDE;  // [256][72]

    const int b   = blockIdx.x;
    const int tid = threadIdx.x;

    const float* kg = g_k + b * (CONTEXT * HD);
    const float* vg = g_v + b * (CONTEXT * HD);

    #pragma unroll
    for (int i = 0; i < 16; i++) {
        int fi = tid + i * 256;          // 4096 float4s per array
        int r  = fi >> 4;
        int c4 = (fi & 15) * 4;
        *reinterpret_cast<float4*>(&kS[r * KSTRIDE + c4]) =
            *reinterpret_cast<const float4*>(&kg[r * HD + c4]);
        *reinterpret_cast<float4*>(&vS[r * VSTRIDE + c4]) =
            *reinterpret_cast<const float4*>(&vg[r * HD + c4]);
    }
    __syncthreads();

    const int lane = tid & 31;
    const int warp = tid >> 5;
    const int g    = lane >> 2;
    const int c    = lane & 3;
    const float L2E = 1.44269504f;

    for (int pass = 0; pass < 2; pass++) {
        const int t = pass ? (15 - warp) : warp;   // q-tile, rows [16t, 16t+16)

        const float* qg = g_q + (b * CONTEXT + t * 16) * HD;
        unsigned qa[8][4];
        #pragma unroll
        for (int kt = 0; kt < 8; kt++) {
            int col = kt * 8 + c;
            qa[kt][0] = __float_as_uint(qg[g * HD + col]);
            qa[kt][1] = __float_as_uint(qg[(g + 8) * HD + col]);
            qa[kt][2] = __float_as_uint(qg[g * HD + col + 4]);
            qa[kt][3] = __float_as_uint(qg[(g + 8) * HD + col + 4]);
        }

        float o[8][4];
        #pragma unroll
        for (int nt = 0; nt < 8; nt++)
            #pragma unroll
            for (int r = 0; r < 4; r++) o[nt][r] = 0.f;

        float m0 = -1e30f, m1 = -1e30f, l0 = 0.f, l1 = 0.f;
        const int diag = t >> 2;
        const int nch  = diag + 1;

        for (int jc = 0; jc < nch; jc++) {
            // ---- scores: kt-outer so the 8 s[nt] accumulators stay independent
            float s[8][4];
            #pragma unroll
            for (int nt = 0; nt < 8; nt++)
                #pragma unroll
                for (int r = 0; r < 4; r++) s[nt][r] = 0.f;

            #pragma unroll
            for (int kt = 0; kt < 8; kt++) {
                #pragma unroll
                for (int nt = 0; nt < 8; nt++) {
                    const int kr = (jc * 64 + nt * 8 + g) * KSTRIDE + kt * 8 + c;
                    unsigned bf[2];
                    bf[0] = __float_as_uint(kS[kr]);
                    bf[1] = __float_as_uint(kS[kr + 4]);
                    mma_tf32(s[nt], qa[kt], bf);
                }
            }

            // ---- causal mask (diagonal chunk only) ----
            if (jc == diag) {
                int rowg = t * 16 + g;
                #pragma unroll
                for (int nt = 0; nt < 8; nt++) {
                    int colg = jc * 64 + nt * 8 + 2 * c;
                    if (colg     > rowg)     s[nt][0] = -1e30f;
                    if (colg + 1 > rowg)     s[nt][1] = -1e30f;
                    if (colg     > rowg + 8) s[nt][2] = -1e30f;
                    if (colg + 1 > rowg + 8) s[nt][3] = -1e30f;
                }
            }

            // ---- online softmax update ----
            float mx0 = -1e30f, mx1 = -1e30f;
            #pragma unroll
            for (int nt = 0; nt < 8; nt++) {
                mx0 = fmaxf(mx0, fmaxf(s[nt][0], s[nt][1]));
                mx1 = fmaxf(mx1, fmaxf(s[nt][2], s[nt][3]));
            }
            mx0 = fmaxf(mx0, __shfl_xor_sync(0xffffffffu, mx0, 1));
            mx0 = fmaxf(mx0, __shfl_xor_sync(0xffffffffu, mx0, 2));
            mx1 = fmaxf(mx1, __shfl_xor_sync(0xffffffffu, mx1, 1));
            mx1 = fmaxf(mx1, __shfl_xor_sync(0xffffffffu, mx1, 2));

            float mn0 = fmaxf(m0, mx0), mn1 = fmaxf(m1, mx1);
            float al0 = exp2f((m0 - mn0) * L2E);
            float al1 = exp2f((m1 - mn1) * L2E);
            m0 = mn0; m1 = mn1;

            float rs0 = 0.f, rs1 = 0.f;
            #pragma unroll
            for (int nt = 0; nt < 8; nt++) {
                s[nt][0] = exp2f((s[nt][0] - mn0) * L2E);
                s[nt][1] = exp2f((s[nt][1] - mn0) * L2E);
                s[nt][2] = exp2f((s[nt][2] - mn1) * L2E);
                s[nt][3] = exp2f((s[nt][3] - mn1) * L2E);
                rs0 += s[nt][0] + s[nt][1];
                rs1 += s[nt][2] + s[nt][3];
            }
            l0 = l0 * al0 + rs0;
            l1 = l1 * al1 + rs1;
            #pragma unroll
            for (int nt = 0; nt < 8; nt++) {
                o[nt][0] *= al0; o[nt][1] *= al0;
                o[nt][2] *= al1; o[nt][3] *= al1;
            }

            // ---- O += P @ V (C-frag -> A-frag via intra-quad shuffles) ----
            const int srcA = (lane & ~3) | (c >> 1);
            const int srcB = srcA + 2;
            const bool odd = (c & 1);
            #pragma unroll
            for (int kt = 0; kt < 8; kt++) {
                float v0 = __shfl_sync(0xffffffffu, s[kt][0], srcA);
                float v1 = __shfl_sync(0xffffffffu, s[kt][1], srcA);
                float v2 = __shfl_sync(0xffffffffu, s[kt][2], srcA);
                float v3 = __shfl_sync(0xffffffffu, s[kt][3], srcA);
                float w0 = __shfl_sync(0xffffffffu, s[kt][0], srcB);
                float w1 = __shfl_sync(0xffffffffu, s[kt][1], srcB);
                float w2 = __shfl_sync(0xffffffffu, s[kt][2], srcB);
                float w3 = __shfl_sync(0xffffffffu, s[kt][3], srcB);
                unsigned pa[4];
                pa[0] = f2tf(odd ? v1 : v0);
                pa[1] = f2tf(odd ? v3 : v2);
                pa[2] = f2tf(odd ? w1 : w0);
                pa[3] = f2tf(odd ? w3 : w2);

                const int krow0 = (jc * 64 + kt * 8 + c) * VSTRIDE;
                const int krow1 = (jc * 64 + kt * 8 + c + 4) * VSTRIDE;
                #pragma unroll
                for (int nt = 0; nt < 8; nt++) {
                    unsigned bv[2];
                    bv[0] = __float_as_uint(vS[krow0 + nt * 8 + g]);
                    bv[1] = __float_as_uint(vS[krow1 + nt * 8 + g]);
                    mma_tf32(o[nt], pa, bv);
                }
            }
        }

        // ---- finalize ----
        l0 += __shfl_xor_sync(0xffffffffu, l0, 1);
        l0 += __shfl_xor_sync(0xffffffffu, l0, 2);
        l1 += __shfl_xor_sync(0xffffffffu, l1, 1);
        l1 += __shfl_xor_sync(0xffffffffu, l1, 2);
        float inv0 = 1.f / l0, inv1 = 1.f / l1;

        float* og = out + (b * CONTEXT + t * 16) * HD;
        #pragma unroll
        for (int nt = 0; nt < 8; nt++) {
            int col = nt * 8 + 2 * c;
            float2 u0, u1;
            u0.x = o[nt][0] * inv0; u0.y = o[nt][1] * inv0;
            u1.x = o[nt][2] * inv1; u1.y = o[nt][3] * inv1;
            *reinterpret_cast<float2*>(&og[g * HD + col])       = u0;
            *reinterpret_cast<float2*>(&og[(g + 8) * HD + col]) = u1;
        }
    }
}

// ---------------------------------------------------------------------------
extern "C" void kernel_launch(void* const* d_in, const int* in_sizes, int n_in,
                              void* d_out, int out_size)
{
    (void)in_sizes; (void)n_in; (void)out_size;
    const float* x  = (const float*)d_in[0];
    const float* Wq = (const float*)d_in[1];
    const float* Wk = (const float*)d_in[2];
    const float* Wv = (const float*)d_in[3];
    float* out = (float*)d_out;

    cudaFuncSetAttribute(qkv_fused,
                         cudaFuncAttributeMaxDynamicSharedMemorySize, QKV_SMEM);
    cudaFuncSetAttribute(attn_kernel,
                         cudaFuncAttributeMaxDynamicSharedMemorySize, ATTN_SMEM);

    qkv_fused<<<BT / 128, 512, QKV_SMEM>>>(x, Wq, Wk, Wv);
    attn_kernel<<<NBATCH, 256, ATTN_SMEM>>>(out);
}